// round 1
// baseline (speedup 1.0000x reference)
#include <cuda_runtime.h>

// ---------------------------------------------------------------------------
// EfmLSTM: x_proj GEMM (fp32, f32x2-packed FFMA) + persistent recurrent scan
// with recurrent weights in registers and fused forget-gate projection.
// ---------------------------------------------------------------------------

#define B_   256
#define T_   1024
#define D_   256
#define U_   128
#define G_   384   // 3*U
#define SIG_ 20
#define M_   (B_ * T_)

typedef unsigned long long ull;

// 402 MB scratch for x_proj [B,T,3U]
__device__ float g_xproj[(size_t)M_ * G_];

// ---- packed f32x2 helpers (sm_103a FFMA2) ----
__device__ __forceinline__ ull pack2f(float lo, float hi) {
    ull r;
    asm("mov.b64 %0, {%1,%2};" : "=l"(r) : "f"(lo), "f"(hi));
    return r;
}
__device__ __forceinline__ void unpack2f(ull v, float& lo, float& hi) {
    asm("mov.b64 {%0,%1}, %2;" : "=f"(lo), "=f"(hi) : "l"(v));
}
__device__ __forceinline__ ull ffma2(ull a, ull b, ull c) {
    ull d;
    asm("fma.rn.f32x2 %0, %1, %2, %3;" : "=l"(d) : "l"(a), "l"(b), "l"(c));
    return d;
}

// ---- fast activations (MUFU-based, rel err ~1e-6, saturate correctly) ----
__device__ __forceinline__ float fsig(float x) {
    return __fdividef(1.0f, 1.0f + __expf(-x));
}
__device__ __forceinline__ float ftanh(float x) {
    // 1 - 2/(e^{2x}+1): exp overflow to +inf gives 1.0, underflow gives -1.0
    return 1.0f - 2.0f * __fdividef(1.0f, __expf(2.0f * x) + 1.0f);
}

// ===========================================================================
// Kernel 1: x_proj = inputs[M,256] @ input_kernel[256,384]  (fp32)
// Classic 128x128x16 tile, 256 threads, 8x8 microtile, f32x2 accumulation.
// ===========================================================================
#define BM 128
#define BN 128
#define BK 16

__global__ __launch_bounds__(256, 1)
void xproj_gemm(const float* __restrict__ A, const float* __restrict__ Bw) {
    __shared__ __align__(16) float As[BK][BM];   // transposed A tile
    __shared__ __align__(16) float Bs[BK][BN];

    const int tid = threadIdx.x;
    const int bn  = blockIdx.x;   // 0..2
    const int bm  = blockIdx.y;   // 0..2047
    const int K = D_, N = G_;

    // global load mapping
    const int arow = tid >> 2;           // 0..63 (and +64)
    const int acol = (tid & 3) << 2;     // 0,4,8,12
    const int brow = tid >> 5;           // 0..7 (and +8)
    const int bcol = (tid & 31) << 2;    // 0..124

    // compute mapping
    const int tx = tid & 15, ty = tid >> 4;

    const float* Ab = A + (size_t)bm * BM * K;
    const float* Bb = Bw + bn * BN;

    // register-buffered prefetch of first tiles
    float4 a0r = *(const float4*)&Ab[(size_t)arow * K + acol];
    float4 a1r = *(const float4*)&Ab[(size_t)(arow + 64) * K + acol];
    float4 b0r = *(const float4*)&Bb[(size_t)brow * N + bcol];
    float4 b1r = *(const float4*)&Bb[(size_t)(brow + 8) * N + bcol];

    ull acc[8][4];
#pragma unroll
    for (int i = 0; i < 8; i++)
#pragma unroll
        for (int j = 0; j < 4; j++) acc[i][j] = 0ULL;  // (0.0f, 0.0f)

    for (int kt = 0; kt < K; kt += BK) {
        // commit prefetched tiles to SMEM (A transposed)
        As[acol + 0][arow]      = a0r.x;
        As[acol + 1][arow]      = a0r.y;
        As[acol + 2][arow]      = a0r.z;
        As[acol + 3][arow]      = a0r.w;
        As[acol + 0][arow + 64] = a1r.x;
        As[acol + 1][arow + 64] = a1r.y;
        As[acol + 2][arow + 64] = a1r.z;
        As[acol + 3][arow + 64] = a1r.w;
        *(float4*)&Bs[brow][bcol]     = b0r;
        *(float4*)&Bs[brow + 8][bcol] = b1r;
        __syncthreads();

        // prefetch next tiles (hidden under ~2000 cycles of FFMA)
        if (kt + BK < K) {
            a0r = *(const float4*)&Ab[(size_t)arow * K + (kt + BK) + acol];
            a1r = *(const float4*)&Ab[(size_t)(arow + 64) * K + (kt + BK) + acol];
            b0r = *(const float4*)&Bb[(size_t)(kt + BK + brow) * N + bcol];
            b1r = *(const float4*)&Bb[(size_t)(kt + BK + brow + 8) * N + bcol];
        }

#pragma unroll
        for (int k = 0; k < BK; k++) {
            float4 av0 = *(const float4*)&As[k][ty * 4];
            float4 av1 = *(const float4*)&As[k][64 + ty * 4];
            ulonglong2 bv0 = *(const ulonglong2*)&Bs[k][tx * 4];
            ulonglong2 bv1 = *(const ulonglong2*)&Bs[k][64 + tx * 4];
            float am[8] = {av0.x, av0.y, av0.z, av0.w,
                           av1.x, av1.y, av1.z, av1.w};
#pragma unroll
            for (int i = 0; i < 8; i++) {
                ull ap = pack2f(am[i], am[i]);
                acc[i][0] = ffma2(ap, bv0.x, acc[i][0]);
                acc[i][1] = ffma2(ap, bv0.y, acc[i][1]);
                acc[i][2] = ffma2(ap, bv1.x, acc[i][2]);
                acc[i][3] = ffma2(ap, bv1.y, acc[i][3]);
            }
        }
        __syncthreads();
    }

    // epilogue: write C tile
#pragma unroll
    for (int i = 0; i < 8; i++) {
        int ml = (i < 4) ? (ty * 4 + i) : (64 + ty * 4 + (i - 4));
        size_t row = (size_t)(bm * BM + ml) * N + bn * BN;
        float4 v;
        unpack2f(acc[i][0], v.x, v.y);
        unpack2f(acc[i][1], v.z, v.w);
        *(float4*)&g_xproj[row + tx * 4] = v;
        unpack2f(acc[i][2], v.x, v.y);
        unpack2f(acc[i][3], v.z, v.w);
        *(float4*)&g_xproj[row + 64 + tx * 4] = v;
    }
}

// ===========================================================================
// Kernel 2: persistent recurrent scan.
// 128 CTAs x 384 threads; each CTA owns 2 batch rows; thread j owns gate
// column j with W_r[:,j] held as 64 packed f32x2 registers.
// Fuses f_t = sigmoid(sig @ forget_kernel + b_f) into the state update.
// ===========================================================================
__global__ __launch_bounds__(384, 1)
void efm_scan(const float* __restrict__ sigs,   // [B,T,SIG]
              const float* __restrict__ rk,     // [U,3U]
              const float* __restrict__ fk,     // [SIG,U]
              const float* __restrict__ bias,   // [4U]
              float* __restrict__ out)          // [B,T,U]
{
    const int j  = threadIdx.x;
    const int r0 = blockIdx.x * 2;

    __shared__ __align__(16) float sh[2][U_];        // h state per row
    __shared__ __align__(16) float sg[2][G_];        // activated gates
    __shared__ __align__(16) float sF[SIG_][U_];     // forget kernel
    __shared__ float ssig[2][2][SIG_];               // [buf][row][s]

    // --- load W_r column j as packed k-pairs (coalesced, one-time) ---
    ull W[64];
#pragma unroll
    for (int k2 = 0; k2 < 64; k2++)
        W[k2] = pack2f(rk[(2 * k2) * G_ + j], rk[(2 * k2 + 1) * G_ + j]);

    // gate bias for this column: [b_i | b_c | b_o] per reference split
    float gb;
    if (j < U_)          gb = bias[j];                    // b_i
    else if (j < 2 * U_) gb = bias[2 * U_ + (j - U_)];    // b_c
    else                 gb = bias[3 * U_ + (j - 2 * U_)];// b_o

    for (int idx = j; idx < SIG_ * U_; idx += 384)
        (&sF[0][0])[idx] = fk[idx];

    if (j < U_) { sh[0][j] = 0.0f; sh[1][j] = 0.0f; }

    // phase-B role: threads 0..127 -> row0 unit j; 128..255 -> row1 unit j-128
    const int browB = (j < U_) ? 0 : 1;
    const int u = j & (U_ - 1);
    float creg = 0.0f;
    const float bf = bias[U_ + u];   // b_f

    // sig loader threads: 256..295 (row 0: s 0..19, row 1: s 0..19)
    const bool sigThr = (j >= 256 && j < 256 + 2 * SIG_);
    int srow = 0, ss = 0;
    if (sigThr) { srow = (j - 256) / SIG_; ss = (j - 256) % SIG_; }

    // prologue: x(0), sig(0)
    float x0 = g_xproj[((size_t)r0 * T_) * G_ + j];
    float x1 = g_xproj[((size_t)(r0 + 1) * T_) * G_ + j];
    if (sigThr)
        ssig[0][srow][ss] = sigs[((size_t)(r0 + srow) * T_) * SIG_ + ss];
    __syncthreads();

    for (int t = 0; t < T_; t++) {
        // --- prefetch t+1 (hidden under the GEMV) ---
        float nx0 = 0.0f, nx1 = 0.0f, nsig = 0.0f;
        if (t + 1 < T_) {
            nx0 = g_xproj[((size_t)r0 * T_ + t + 1) * G_ + j];
            nx1 = g_xproj[((size_t)(r0 + 1) * T_ + t + 1) * G_ + j];
            if (sigThr)
                nsig = sigs[((size_t)(r0 + srow) * T_ + t + 1) * SIG_ + ss];
        }

        // --- phase A: gates for both rows (packed GEMV, 4 accumulators) ---
        const ulonglong2* hp0 = (const ulonglong2*)sh[0];
        const ulonglong2* hp1 = (const ulonglong2*)sh[1];
        ull acA0 = 0ULL, acB0 = 0ULL, acA1 = 0ULL, acB1 = 0ULL;
#pragma unroll
        for (int q = 0; q < 32; q++) {
            ulonglong2 h0 = hp0[q];
            ulonglong2 h1 = hp1[q];
            acA0 = ffma2(h0.x, W[2 * q],     acA0);
            acB0 = ffma2(h0.y, W[2 * q + 1], acB0);
            acA1 = ffma2(h1.x, W[2 * q],     acA1);
            acB1 = ffma2(h1.y, W[2 * q + 1], acB1);
        }
        float lo, hi;
        unpack2f(acA0, lo, hi); float g0 = lo + hi;
        unpack2f(acB0, lo, hi); g0 += lo + hi;
        g0 += x0 + gb;
        unpack2f(acA1, lo, hi); float g1 = lo + hi;
        unpack2f(acB1, lo, hi); g1 += lo + hi;
        g1 += x1 + gb;

        float act0, act1;
        if (j < U_ || j >= 2 * U_) { act0 = fsig(g0);  act1 = fsig(g1);  }
        else                       { act0 = ftanh(g0); act1 = ftanh(g1); }
        sg[0][j] = act0;
        sg[1][j] = act1;

        if (sigThr && (t + 1 < T_))
            ssig[(t + 1) & 1][srow][ss] = nsig;

        __syncthreads();

        // --- phase B: fused forget gate + state update ---
        if (j < 2 * U_) {
            float fa = bf;
#pragma unroll
            for (int s = 0; s < SIG_; s++)
                fa += ssig[t & 1][browB][s] * sF[s][u];
            float f   = fsig(fa);
            float ig  = sg[browB][u];
            float ch  = sg[browB][U_ + u];
            float og  = sg[browB][2 * U_ + u];
            creg = f * creg + ig * ch;
            float hn = og * ftanh(creg);
            sh[browB][u] = hn;
            out[((size_t)(r0 + browB) * T_ + t) * U_ + u] = hn;
        }

        x0 = nx0;
        x1 = nx1;
        __syncthreads();
    }
}

// ===========================================================================
extern "C" void kernel_launch(void* const* d_in, const int* in_sizes, int n_in,
                              void* d_out, int out_size) {
    const float* inputs = (const float*)d_in[0];   // [B,T,D]
    const float* sigs   = (const float*)d_in[1];   // [B,T,SIG]
    const float* ik     = (const float*)d_in[2];   // [D,3U]
    const float* rk     = (const float*)d_in[3];   // [U,3U]
    const float* fk     = (const float*)d_in[4];   // [SIG,U]
    const float* bias   = (const float*)d_in[5];   // [4U]
    float* out = (float*)d_out;                    // [B,T,U]

    dim3 gemm_grid(G_ / BN, M_ / BM);   // (3, 2048)
    xproj_gemm<<<gemm_grid, 256>>>(inputs, ik);

    efm_scan<<<B_ / 2, 384>>>(sigs, rk, fk, bias, out);
}